// round 14
// baseline (speedup 1.0000x reference)
#include <cuda_runtime.h>
#include <cuda_bf16.h>

#define RES 7
#define NROI 1024
#define NCH 256

// ---------------- per-roi precomputed tables ----------------
__device__ int4   g_lbw[NROI];         // lvl, batch, vector-path flag, pad
__device__ int4   g_yrow[NROI][8];     // 4 row offsets (premultiplied by W) per py
__device__ float4 g_ywt[NROI][8];      // y weights (*0.5, validity folded)
__device__ int4   g_xcol[NROI][8];     // 4 col offsets per px (scalar path)
__device__ float4 g_xwt[NROI][8];      // x weights (*0.5, validity folded)
__device__ int    g_xbase[NROI][8];    // aligned 8-window base per px (vector path)
__device__ float4 g_xw8a[NROI][8];     // window weights [0..3]
__device__ float4 g_xw8b[NROI][8];     // window weights [4..7]

__device__ __forceinline__ void samp(float v, int size,
                                     int& lo, int& hi, float& wl, float& wh) {
    bool valid = (v >= -1.0f) && (v <= (float)size);
    float v0 = fmaxf(v, 0.0f);
    int l = (int)floorf(v0);
    float fr;
    if (l >= size - 1) { l = size - 1; hi = size - 1; fr = 0.0f; }
    else               { hi = l + 1; fr = v0 - (float)l; }
    lo = l;
    wl = valid ? (1.0f - fr) : 0.0f;
    wh = valid ? fr : 0.0f;
}

__global__ void setup_kernel(const float* __restrict__ p0,
                             const float* __restrict__ p1) {
    int r = blockIdx.x * blockDim.x + threadIdx.x;
    if (r >= NROI) return;
    const float* p = (r < 512) ? (p0 + r * 4) : (p1 + (r - 512) * 4);
    float x1 = p[0], y1 = p[1], x2 = p[2], y2 = p[3];
    float area = (x2 - x1 + 1.0f) * (y2 - y1 + 1.0f);
    float sz = sqrtf(area);
    float lv = floorf(4.0f + log2f(sz / 224.0f + 1e-6f));
    lv = fminf(fmaxf(lv, 2.0f), 5.0f);
    int lvl = (int)lv - 2;
    float scale = 0.25f / (float)(1 << lvl);
    int H, W;
    switch (lvl) {
        case 0:  H = 200; W = 200; break;
        case 1:  H = 100; W = 100; break;
        case 2:  H = 50;  W = 50;  break;
        default: H = 25;  W = 25;  break;
    }
    float x1s = x1 * scale, y1s = y1 * scale;
    float rw = fmaxf(x2 * scale - x1s, 1.0f);
    float rh = fmaxf(y2 * scale - y1s, 1.0f);
    float bw = rw / 7.0f, bh = rh / 7.0f;

    int vec_ok = (W % 4 == 0) ? 1 : 0;

#pragma unroll
    for (int q = 0; q < 7; q++) {
        {   // y samples 2q, 2q+1
            float s0 = y1s + ((float)(2 * q) + 0.5f) * 0.5f * bh;
            float s1 = y1s + ((float)(2 * q + 1) + 0.5f) * 0.5f * bh;
            int l0, h0, l1, h1; float a0, b0, a1, b1;
            samp(s0, H, l0, h0, a0, b0);
            samp(s1, H, l1, h1, a1, b1);
            g_yrow[r][q] = make_int4(l0 * W, h0 * W, l1 * W, h1 * W);
            g_ywt[r][q]  = make_float4(a0 * 0.5f, b0 * 0.5f, a1 * 0.5f, b1 * 0.5f);
        }
        {   // x samples 2q, 2q+1
            float s0 = x1s + ((float)(2 * q) + 0.5f) * 0.5f * bw;
            float s1 = x1s + ((float)(2 * q + 1) + 0.5f) * 0.5f * bw;
            int l0, h0, l1, h1; float a0, b0, a1, b1;
            samp(s0, W, l0, h0, a0, b0);
            samp(s1, W, l1, h1, a1, b1);
            g_xcol[r][q] = make_int4(l0, h0, l1, h1);
            float w0 = a0 * 0.5f, w1 = b0 * 0.5f, w2 = a1 * 0.5f, w3 = b1 * 0.5f;
            g_xwt[r][q]  = make_float4(w0, w1, w2, w3);

            // 8-wide aligned window + scattered weights
            int base = l0 & ~3;
            if (base > W - 8) base = W - 8;
            if (base < 0) base = 0;
            float w8[8] = {0, 0, 0, 0, 0, 0, 0, 0};
            int o0 = l0 - base, o1 = h0 - base, o2 = l1 - base, o3 = h1 - base;
            int omax = max(max(o0, o1), max(o2, o3));
            int omin = min(min(o0, o1), min(o2, o3));
            if (omax > 7 || omin < 0) vec_ok = 0;
            else {
                w8[o0] += w0; w8[o1] += w1; w8[o2] += w2; w8[o3] += w3;
            }
            g_xbase[r][q] = base;
            g_xw8a[r][q] = make_float4(w8[0], w8[1], w8[2], w8[3]);
            g_xw8b[r][q] = make_float4(w8[4], w8[5], w8[6], w8[7]);
        }
    }
    g_lbw[r] = make_int4(lvl, (r < 512) ? 0 : 1, vec_ok, 0);
}

__device__ __forceinline__ float dot8(const float* __restrict__ p,
                                      float4 wa, float4 wb) {
    float4 u = *(const float4*)p;
    float4 v = *(const float4*)(p + 4);
    return u.x * wa.x + u.y * wa.y + u.z * wa.z + u.w * wa.w
         + v.x * wb.x + v.y * wb.y + v.z * wb.z + v.w * wb.w;
}

// grid = (25, NROI): blockIdx.y = roi; e in [0, 6272) = (c in [0,128), bin).
// Each thread computes bin for channels c and c+128.
__global__ __launch_bounds__(256) void pool_kernel(
    const float* __restrict__ f0, const float* __restrict__ f1,
    const float* __restrict__ f2, const float* __restrict__ f3,
    float* __restrict__ out) {

    __shared__ int4   yoS[8];
    __shared__ float4 ywS[8];
    __shared__ int4   xoS[8];
    __shared__ float4 xwS[8];
    __shared__ float4 waS[8], wbS[8];
    __shared__ int    xbS[8];

    const int roi = blockIdx.y;
    const int tid = threadIdx.x;
    if (tid < 8) {
        yoS[tid] = g_yrow[roi][tid];
        ywS[tid] = g_ywt[roi][tid];
        xoS[tid] = g_xcol[roi][tid];
        xwS[tid] = g_xwt[roi][tid];
        waS[tid] = g_xw8a[roi][tid];
        wbS[tid] = g_xw8b[roi][tid];
        xbS[tid] = g_xbase[roi][tid];
    }
    __syncthreads();

    const int e = blockIdx.x * 256 + tid;   // [0, 6272)
    if (e >= 6272) return;
    const int c = e / 49;                   // [0, 128)
    const int bin = e - c * 49;
    const int py = bin / 7;
    const int px = bin - py * 7;

    const int4 lb = g_lbw[roi];
    const float* base; int HW;
    switch (lb.x) {
        case 0:  base = f0; HW = 200 * 200; break;
        case 1:  base = f1; HW = 100 * 100; break;
        case 2:  base = f2; HW = 50 * 50;   break;
        default: base = f3; HW = 25 * 25;   break;
    }

    const int4   yr = yoS[py];
    const float4 wy = ywS[py];

    const float* cb0 = base + ((size_t)lb.y * NCH + c) * HW;
    const float* cb1 = cb0 + (size_t)128 * HW;

    float accA, accB;
    if (lb.z) {
        // ---- vector path: 2x LDG.128 per row, 8-wide weighted dot ----
        const float4 wa = waS[px], wb = wbS[px];
        const int xb = xbS[px];
        const float* a0 = cb0 + yr.x + xb; const float* a1 = cb0 + yr.y + xb;
        const float* a2 = cb0 + yr.z + xb; const float* a3 = cb0 + yr.w + xb;
        const float* b0 = cb1 + yr.x + xb; const float* b1 = cb1 + yr.y + xb;
        const float* b2 = cb1 + yr.z + xb; const float* b3 = cb1 + yr.w + xb;
        float s0 = dot8(a0, wa, wb);
        float t0 = dot8(b0, wa, wb);
        float s1 = dot8(a1, wa, wb);
        float t1 = dot8(b1, wa, wb);
        float s2 = dot8(a2, wa, wb);
        float t2 = dot8(b2, wa, wb);
        float s3 = dot8(a3, wa, wb);
        float t3 = dot8(b3, wa, wb);
        accA = wy.x * s0 + wy.y * s1 + wy.z * s2 + wy.w * s3;
        accB = wy.x * t0 + wy.y * t1 + wy.z * t2 + wy.w * t3;
    } else {
        // ---- scalar fallback (R13 path) ----
        const int4   xc = xoS[px];
        const float4 wx = xwS[px];
        const float* a0 = cb0 + yr.x; const float* a1 = cb0 + yr.y;
        const float* a2 = cb0 + yr.z; const float* a3 = cb0 + yr.w;
        const float* b0 = cb1 + yr.x; const float* b1 = cb1 + yr.y;
        const float* b2 = cb1 + yr.z; const float* b3 = cb1 + yr.w;
        float s0 = wx.x * __ldg(a0 + xc.x) + wx.y * __ldg(a0 + xc.y)
                 + wx.z * __ldg(a0 + xc.z) + wx.w * __ldg(a0 + xc.w);
        float t0 = wx.x * __ldg(b0 + xc.x) + wx.y * __ldg(b0 + xc.y)
                 + wx.z * __ldg(b0 + xc.z) + wx.w * __ldg(b0 + xc.w);
        float s1 = wx.x * __ldg(a1 + xc.x) + wx.y * __ldg(a1 + xc.y)
                 + wx.z * __ldg(a1 + xc.z) + wx.w * __ldg(a1 + xc.w);
        float t1 = wx.x * __ldg(b1 + xc.x) + wx.y * __ldg(b1 + xc.y)
                 + wx.z * __ldg(b1 + xc.z) + wx.w * __ldg(b1 + xc.w);
        float s2 = wx.x * __ldg(a2 + xc.x) + wx.y * __ldg(a2 + xc.y)
                 + wx.z * __ldg(a2 + xc.z) + wx.w * __ldg(a2 + xc.w);
        float t2 = wx.x * __ldg(b2 + xc.x) + wx.y * __ldg(b2 + xc.y)
                 + wx.z * __ldg(b2 + xc.z) + wx.w * __ldg(b2 + xc.w);
        float s3 = wx.x * __ldg(a3 + xc.x) + wx.y * __ldg(a3 + xc.y)
                 + wx.z * __ldg(a3 + xc.z) + wx.w * __ldg(a3 + xc.w);
        float t3 = wx.x * __ldg(b3 + xc.x) + wx.y * __ldg(b3 + xc.y)
                 + wx.z * __ldg(b3 + xc.z) + wx.w * __ldg(b3 + xc.w);
        accA = wy.x * s0 + wy.y * s1 + wy.z * s2 + wy.w * s3;
        accB = wy.x * t0 + wy.y * t1 + wy.z * t2 + wy.w * t3;
    }

    size_t o = ((size_t)roi * NCH + c) * 49 + bin;
    out[o] = accA;
    out[o + (size_t)128 * 49] = accB;
}

extern "C" void kernel_launch(void* const* d_in, const int* in_sizes, int n_in,
                              void* d_out, int out_size) {
    const float* f0 = (const float*)d_in[0];
    const float* f1 = (const float*)d_in[1];
    const float* f2 = (const float*)d_in[2];
    const float* f3 = (const float*)d_in[3];
    // d_in[4] = feat4 (13x13) — never selected by the 4 RATIOS; unused.
    const float* p0 = (const float*)d_in[5];
    const float* p1 = (const float*)d_in[6];
    float* out = (float*)d_out;

    setup_kernel<<<4, 256>>>(p0, p1);
    dim3 grid(25, NROI);
    pool_kernel<<<grid, 256>>>(f0, f1, f2, f3, out);
}

// round 16
// speedup vs baseline: 1.0577x; 1.0577x over previous
#include <cuda_runtime.h>
#include <cuda_bf16.h>

#define RES 7
#define NROI 1024
#define NCH 256

// ---------------- per-roi precomputed tables ----------------
__device__ int4   g_lbw[NROI];         // lvl, batch, vector-path flag, pad
__device__ int4   g_yrow[NROI][8];     // 4 row offsets (premultiplied by W) per py
__device__ float4 g_ywt[NROI][8];      // y weights (*0.5, validity folded)
__device__ int4   g_xcol[NROI][8];     // 4 col offsets per px (scalar path)
__device__ float4 g_xwt[NROI][8];      // x weights (*0.5, validity folded)
__device__ int    g_xbase[NROI][8];    // aligned 8-window base per px (vector path)
__device__ float4 g_xw8a[NROI][8];     // window weights [0..3]
__device__ float4 g_xw8b[NROI][8];     // window weights [4..7]

__device__ __forceinline__ void samp(float v, int size,
                                     int& lo, int& hi, float& wl, float& wh) {
    bool valid = (v >= -1.0f) && (v <= (float)size);
    float v0 = fmaxf(v, 0.0f);
    int l = (int)floorf(v0);
    float fr;
    if (l >= size - 1) { l = size - 1; hi = size - 1; fr = 0.0f; }
    else               { hi = l + 1; fr = v0 - (float)l; }
    lo = l;
    wl = valid ? (1.0f - fr) : 0.0f;
    wh = valid ? fr : 0.0f;
}

__global__ void setup_kernel(const float* __restrict__ p0,
                             const float* __restrict__ p1) {
    int r = blockIdx.x * blockDim.x + threadIdx.x;
    if (r >= NROI) return;
    const float* p = (r < 512) ? (p0 + r * 4) : (p1 + (r - 512) * 4);
    float x1 = p[0], y1 = p[1], x2 = p[2], y2 = p[3];
    float area = (x2 - x1 + 1.0f) * (y2 - y1 + 1.0f);
    float sz = sqrtf(area);
    float lv = floorf(4.0f + log2f(sz / 224.0f + 1e-6f));
    lv = fminf(fmaxf(lv, 2.0f), 5.0f);
    int lvl = (int)lv - 2;
    float scale = 0.25f / (float)(1 << lvl);
    int H, W;
    switch (lvl) {
        case 0:  H = 200; W = 200; break;
        case 1:  H = 100; W = 100; break;
        case 2:  H = 50;  W = 50;  break;
        default: H = 25;  W = 25;  break;
    }
    float x1s = x1 * scale, y1s = y1 * scale;
    float rw = fmaxf(x2 * scale - x1s, 1.0f);
    float rh = fmaxf(y2 * scale - y1s, 1.0f);
    float bw = rw / 7.0f, bh = rh / 7.0f;

    int vec_ok = (W % 4 == 0 && W >= 8) ? 1 : 0;

#pragma unroll
    for (int q = 0; q < 7; q++) {
        {   // y samples 2q, 2q+1
            float s0 = y1s + ((float)(2 * q) + 0.5f) * 0.5f * bh;
            float s1 = y1s + ((float)(2 * q + 1) + 0.5f) * 0.5f * bh;
            int l0, h0, l1, h1; float a0, b0, a1, b1;
            samp(s0, H, l0, h0, a0, b0);
            samp(s1, H, l1, h1, a1, b1);
            g_yrow[r][q] = make_int4(l0 * W, h0 * W, l1 * W, h1 * W);
            g_ywt[r][q]  = make_float4(a0 * 0.5f, b0 * 0.5f, a1 * 0.5f, b1 * 0.5f);
        }
        {   // x samples 2q, 2q+1
            float s0 = x1s + ((float)(2 * q) + 0.5f) * 0.5f * bw;
            float s1 = x1s + ((float)(2 * q + 1) + 0.5f) * 0.5f * bw;
            int l0, h0, l1, h1; float a0, b0, a1, b1;
            samp(s0, W, l0, h0, a0, b0);
            samp(s1, W, l1, h1, a1, b1);
            g_xcol[r][q] = make_int4(l0, h0, l1, h1);
            float w0 = a0 * 0.5f, w1 = b0 * 0.5f, w2 = a1 * 0.5f, w3 = b1 * 0.5f;
            g_xwt[r][q]  = make_float4(w0, w1, w2, w3);

            // 8-wide aligned window + scattered weights
            int base = l0 & ~3;
            if (base > W - 8) base = W - 8;
            if (base < 0) base = 0;
            float w8[8] = {0, 0, 0, 0, 0, 0, 0, 0};
            int o0 = l0 - base, o1 = h0 - base, o2 = l1 - base, o3 = h1 - base;
            int omax = max(max(o0, o1), max(o2, o3));
            int omin = min(min(o0, o1), min(o2, o3));
            if (omax > 7 || omin < 0) vec_ok = 0;
            else {
                w8[o0] += w0; w8[o1] += w1; w8[o2] += w2; w8[o3] += w3;
            }
            g_xbase[r][q] = base;
            g_xw8a[r][q] = make_float4(w8[0], w8[1], w8[2], w8[3]);
            g_xw8b[r][q] = make_float4(w8[4], w8[5], w8[6], w8[7]);
        }
    }
    g_lbw[r] = make_int4(lvl, (r < 512) ? 0 : 1, vec_ok, 0);
}

__device__ __forceinline__ float dot8(const float* __restrict__ p,
                                      float4 wa, float4 wb) {
    float4 u = *(const float4*)p;
    float4 v = *(const float4*)(p + 4);
    return u.x * wa.x + u.y * wa.y + u.z * wa.z + u.w * wa.w
         + v.x * wb.x + v.y * wb.y + v.z * wb.z + v.w * wb.w;
}

// grid = (25, NROI): blockIdx.y = roi; e in [0, 6272) = (c in [0,128), bin).
// Each thread computes bin for channels c and c+128.
__global__ __launch_bounds__(256) void pool_kernel(
    const float* __restrict__ f0, const float* __restrict__ f1,
    const float* __restrict__ f2, const float* __restrict__ f3,
    float* __restrict__ out) {

    __shared__ int4   yoS[8];
    __shared__ float4 ywS[8];
    __shared__ int4   xoS[8];
    __shared__ float4 xwS[8];
    __shared__ float4 waS[8], wbS[8];
    __shared__ int    xbS[8];

    const int roi = blockIdx.y;
    const int tid = threadIdx.x;
    if (tid < 8) {
        yoS[tid] = g_yrow[roi][tid];
        ywS[tid] = g_ywt[roi][tid];
        xoS[tid] = g_xcol[roi][tid];
        xwS[tid] = g_xwt[roi][tid];
        waS[tid] = g_xw8a[roi][tid];
        wbS[tid] = g_xw8b[roi][tid];
        xbS[tid] = g_xbase[roi][tid];
    }
    __syncthreads();

    const int e = blockIdx.x * 256 + tid;   // [0, 6272)
    if (e >= 6272) return;
    const int c = e / 49;                   // [0, 128)
    const int bin = e - c * 49;
    const int py = bin / 7;
    const int px = bin - py * 7;

    const int4 lb = g_lbw[roi];
    const float* base; int HW;
    switch (lb.x) {
        case 0:  base = f0; HW = 200 * 200; break;
        case 1:  base = f1; HW = 100 * 100; break;
        case 2:  base = f2; HW = 50 * 50;   break;
        default: base = f3; HW = 25 * 25;   break;
    }

    const int4   yr = yoS[py];
    const float4 wy = ywS[py];

    const float* cb0 = base + ((size_t)lb.y * NCH + c) * HW;
    const float* cb1 = cb0 + (size_t)128 * HW;

    float accA, accB;
    if (lb.z) {
        // ---- vector path: per channel, 4 rows x 2 LDG.128, sequential
        // channels to bound live registers ----
        const float4 wa = waS[px], wb = wbS[px];
        const int xb = xbS[px];
        const int   yo[4]  = {yr.x, yr.y, yr.z, yr.w};
        const float wyv[4] = {wy.x, wy.y, wy.z, wy.w};
        accA = 0.0f;
#pragma unroll
        for (int r = 0; r < 4; r++)
            accA += wyv[r] * dot8(cb0 + yo[r] + xb, wa, wb);
        accB = 0.0f;
#pragma unroll
        for (int r = 0; r < 4; r++)
            accB += wyv[r] * dot8(cb1 + yo[r] + xb, wa, wb);
    } else {
        // ---- scalar fallback (R13 path) ----
        const int4   xc = xoS[px];
        const float4 wx = xwS[px];
        const float* a0 = cb0 + yr.x; const float* a1 = cb0 + yr.y;
        const float* a2 = cb0 + yr.z; const float* a3 = cb0 + yr.w;
        const float* b0 = cb1 + yr.x; const float* b1 = cb1 + yr.y;
        const float* b2 = cb1 + yr.z; const float* b3 = cb1 + yr.w;
        float s0 = wx.x * __ldg(a0 + xc.x) + wx.y * __ldg(a0 + xc.y)
                 + wx.z * __ldg(a0 + xc.z) + wx.w * __ldg(a0 + xc.w);
        float t0 = wx.x * __ldg(b0 + xc.x) + wx.y * __ldg(b0 + xc.y)
                 + wx.z * __ldg(b0 + xc.z) + wx.w * __ldg(b0 + xc.w);
        float s1 = wx.x * __ldg(a1 + xc.x) + wx.y * __ldg(a1 + xc.y)
                 + wx.z * __ldg(a1 + xc.z) + wx.w * __ldg(a1 + xc.w);
        float t1 = wx.x * __ldg(b1 + xc.x) + wx.y * __ldg(b1 + xc.y)
                 + wx.z * __ldg(b1 + xc.z) + wx.w * __ldg(b1 + xc.w);
        float s2 = wx.x * __ldg(a2 + xc.x) + wx.y * __ldg(a2 + xc.y)
                 + wx.z * __ldg(a2 + xc.z) + wx.w * __ldg(a2 + xc.w);
        float t2 = wx.x * __ldg(b2 + xc.x) + wx.y * __ldg(b2 + xc.y)
                 + wx.z * __ldg(b2 + xc.z) + wx.w * __ldg(b2 + xc.w);
        float s3 = wx.x * __ldg(a3 + xc.x) + wx.y * __ldg(a3 + xc.y)
                 + wx.z * __ldg(a3 + xc.z) + wx.w * __ldg(a3 + xc.w);
        float t3 = wx.x * __ldg(b3 + xc.x) + wx.y * __ldg(b3 + xc.y)
                 + wx.z * __ldg(b3 + xc.z) + wx.w * __ldg(b3 + xc.w);
        accA = wy.x * s0 + wy.y * s1 + wy.z * s2 + wy.w * s3;
        accB = wy.x * t0 + wy.y * t1 + wy.z * t2 + wy.w * t3;
    }

    size_t o = ((size_t)roi * NCH + c) * 49 + bin;
    out[o] = accA;
    out[o + (size_t)128 * 49] = accB;
}

extern "C" void kernel_launch(void* const* d_in, const int* in_sizes, int n_in,
                              void* d_out, int out_size) {
    const float* f0 = (const float*)d_in[0];
    const float* f1 = (const float*)d_in[1];
    const float* f2 = (const float*)d_in[2];
    const float* f3 = (const float*)d_in[3];
    // d_in[4] = feat4 (13x13) — never selected by the 4 RATIOS; unused.
    const float* p0 = (const float*)d_in[5];
    const float* p1 = (const float*)d_in[6];
    float* out = (float*)d_out;

    setup_kernel<<<4, 256>>>(p0, p1);
    dim3 grid(25, NROI);
    pool_kernel<<<grid, 256>>>(f0, f1, f2, f3, out);
}